// round 10
// baseline (speedup 1.0000x reference)
#include <cuda_runtime.h>
#include <cstdint>

// QPChargeNormalization — 2-CTA cluster per row, DSMEM scalar exchange.
// Per row b (B=4096): n=8192, c=[c_iso|c_aniso], q=[int_iso|int_aniso]
//   h = (sum(charge[b]) - q.c) / (q.q),  x = c + h*q
// Output = [sol_iso (B*4096) | sol_aniso (B*4096)]
//
// Rank 0 of each cluster handles the iso half (+charge), rank 1 the aniso
// half. Each thread holds only 16 data floats -> ~40 regs -> 3 CTAs/SM,
// same total memory traffic as the best single-CTA kernel. The two CTAs
// exchange (qc, qq, Q) partials via st.async into peer SMEM + mbarrier.

#define NT   512
#define NCH  256

__device__ __forceinline__ float dot4(float4 a, float4 b) {
    return fmaf(a.x, b.x, fmaf(a.y, b.y, fmaf(a.z, b.z, a.w * b.w)));
}

__device__ __forceinline__ float4 axpy4(float h, float4 q, float4 c) {
    float4 o;
    o.x = fmaf(h, q.x, c.x);
    o.y = fmaf(h, q.y, c.y);
    o.z = fmaf(h, q.z, c.z);
    o.w = fmaf(h, q.w, c.w);
    return o;
}

__device__ __forceinline__ uint32_t smem_u32(const void* p) {
    return (uint32_t)__cvta_generic_to_shared(p);
}

__device__ __forceinline__ uint32_t mapa_peer(uint32_t local_addr, uint32_t peer) {
    uint32_t r;
    asm volatile("mapa.shared::cluster.u32 %0, %1, %2;"
                 : "=r"(r) : "r"(local_addr), "r"(peer));
    return r;
}

__global__ void __launch_bounds__(NT, 3) __cluster_dims__(2, 1, 1)
qp_cluster_kernel(const float4* __restrict__ c_iso,
                  const float4* __restrict__ c_aniso,
                  const float4* __restrict__ q_iso,
                  const float4* __restrict__ q_aniso,
                  const float*  __restrict__ charge,
                  float4*       __restrict__ out,
                  int B)
{
    const int tid  = threadIdx.x;
    const int wid  = tid >> 5;
    const int lane = tid & 31;

    __shared__ float s_p[48];                    // warp partials
    __shared__ alignas(16) float s_rem[4];       // peer's (qc, qq, Q)
    __shared__ alignas(8)  unsigned long long s_mbar;

    uint32_t rank;
    asm("mov.u32 %0, %%cluster_ctarank;" : "=r"(rank));
    const int r = blockIdx.x >> 1;
    const size_t row4 = (size_t)r * 1024;

    const uint32_t mbar = smem_u32(&s_mbar);

    if (tid == 0) {
        asm volatile("mbarrier.init.shared::cta.b64 [%0], 1;" :: "r"(mbar) : "memory");
    }

    // Half-row loads (issued before the cluster sync so DRAM latency overlaps it).
    const float4* cp = rank ? (c_aniso + row4) : (c_iso + row4);
    const float4* qp = rank ? (q_aniso + row4) : (q_iso + row4);
    float4 c0 = cp[tid];
    float4 c1 = cp[tid + NT];
    float4 q0 = qp[tid];
    float4 q1 = qp[tid + NT];
    float  Qv = (rank == 0 && tid < NCH) ? charge[(size_t)r * NCH + tid] : 0.0f;

    // Both CTAs' mbarriers must be initialized before any st.async targets them.
    asm volatile("barrier.cluster.arrive.aligned;" ::: "memory");
    asm volatile("barrier.cluster.wait.aligned;"   ::: "memory");

    float qc = dot4(q0, c0) + dot4(q1, c1);
    float qq = dot4(q0, q0) + dot4(q1, q1);

    #pragma unroll
    for (int m = 16; m; m >>= 1) {
        qc += __shfl_xor_sync(0xffffffffu, qc, m);
        qq += __shfl_xor_sync(0xffffffffu, qq, m);
        Qv += __shfl_xor_sync(0xffffffffu, Qv, m);
    }
    if (lane == 0) { s_p[wid] = qc; s_p[16 + wid] = qq; s_p[32 + wid] = Qv; }
    __syncthreads();

    // Every warp redundantly reduces the 16 partials -> CTA-local scalars.
    float qc_l = (lane < 16) ? s_p[lane]      : 0.0f;
    float qq_l = (lane < 16) ? s_p[16 + lane] : 0.0f;
    float Q_l  = (lane < 16) ? s_p[32 + lane] : 0.0f;
    #pragma unroll
    for (int m = 8; m; m >>= 1) {
        qc_l += __shfl_xor_sync(0xffffffffu, qc_l, m);
        qq_l += __shfl_xor_sync(0xffffffffu, qq_l, m);
        Q_l  += __shfl_xor_sync(0xffffffffu, Q_l,  m);
    }
    qc_l = __shfl_sync(0xffffffffu, qc_l, 0);
    qq_l = __shfl_sync(0xffffffffu, qq_l, 0);
    Q_l  = __shfl_sync(0xffffffffu, Q_l,  0);

    // Exchange the 3 scalars with the peer CTA: expect 12 bytes on our own
    // barrier, st.async the values into the peer's s_rem + signal its barrier.
    if (tid == 0) {
        asm volatile("mbarrier.arrive.expect_tx.shared::cta.b64 _, [%0], 12;"
                     :: "r"(mbar) : "memory");
        const uint32_t peer       = rank ^ 1u;
        const uint32_t rem_buf    = mapa_peer(smem_u32(s_rem), peer);
        const uint32_t rem_mbar   = mapa_peer(mbar, peer);
        asm volatile("st.async.shared::cluster.mbarrier::complete_tx::bytes.b32 [%0], %1, [%2];"
                     :: "r"(rem_buf),     "f"(qc_l), "r"(rem_mbar) : "memory");
        asm volatile("st.async.shared::cluster.mbarrier::complete_tx::bytes.b32 [%0], %1, [%2];"
                     :: "r"(rem_buf + 4), "f"(qq_l), "r"(rem_mbar) : "memory");
        asm volatile("st.async.shared::cluster.mbarrier::complete_tx::bytes.b32 [%0], %1, [%2];"
                     :: "r"(rem_buf + 8), "f"(Q_l),  "r"(rem_mbar) : "memory");
    }

    // Wait for the peer's scalars (parity 0).
    {
        uint32_t done;
        asm volatile(
            "{\n\t.reg .pred p;\n\t"
            "mbarrier.try_wait.parity.acquire.cta.shared::cta.b64 p, [%1], 0;\n\t"
            "selp.b32 %0, 1, 0, p;\n\t}"
            : "=r"(done) : "r"(mbar) : "memory");
        if (!done) {
            asm volatile(
                "{\n\t.reg .pred P1;\n\t"
                "W_%=:\n\t"
                "mbarrier.try_wait.parity.acquire.cta.shared::cta.b64 P1, [%0], 0, 0x989680;\n\t"
                "@P1 bra.uni D_%=;\n\t"
                "bra.uni W_%=;\n\t"
                "D_%=:\n\t}"
                :: "r"(mbar) : "memory");
        }
    }

    const float h = ((Q_l + s_rem[2]) - (qc_l + s_rem[0])) / (qq_l + s_rem[1]);

    // This CTA writes its own half of the output.
    float4* o = rank ? (out + (size_t)B * 1024 + row4) : (out + row4);
    o[tid]      = axpy4(h, q0, c0);
    o[tid + NT] = axpy4(h, q1, c1);
}

extern "C" void kernel_launch(void* const* d_in, const int* in_sizes, int n_in,
                              void* d_out, int out_size)
{
    const float4* c_iso   = (const float4*)d_in[0];
    const float4* c_aniso = (const float4*)d_in[1];
    const float4* q_iso   = (const float4*)d_in[2];
    const float4* q_aniso = (const float4*)d_in[3];
    const float*  charge  = (const float*) d_in[4];
    float4*       out     = (float4*)d_out;

    const int B = in_sizes[4] / NCH;   // charge is [B, 256]

    qp_cluster_kernel<<<2 * B, NT>>>(c_iso, c_aniso, q_iso, q_aniso,
                                     charge, out, B);
}

// round 11
// speedup vs baseline: 1.5357x; 1.5357x over previous
#include <cuda_runtime.h>

// QPChargeNormalization — R1 architecture (measured best: 55.8us kernel,
// 81.3% DRAM) with the reduction tail shortened to a single barrier.
//
// Per row b (B=4096): n=8192, c=[c_iso|c_aniso], q=[int_iso|int_aniso]
//   h = (sum(charge[b]) - q.c) / (q.q),  x = c + h*q
// Output = [sol_iso (B*4096) | sol_aniso (B*4096)]
//
// One CTA per row, 512 threads, 2 CTAs/SM, all data register-resident
// between the reduction and the axpy (each element crosses HBM once).
// Single __syncthreads per row: warp butterfly -> 16 smem partials ->
// barrier -> every warp redundantly reduces the partials and forms h.

#define NTHREADS 512
#define NCH      256

__device__ __forceinline__ float dot4(float4 a, float4 b) {
    return fmaf(a.x, b.x, fmaf(a.y, b.y, fmaf(a.z, b.z, a.w * b.w)));
}

__device__ __forceinline__ float4 axpy4(float h, float4 q, float4 c) {
    float4 o;
    o.x = fmaf(h, q.x, c.x);
    o.y = fmaf(h, q.y, c.y);
    o.z = fmaf(h, q.z, c.z);
    o.w = fmaf(h, q.w, c.w);
    return o;
}

__global__ void __launch_bounds__(NTHREADS, 2)
qp_charge_norm_kernel(const float4* __restrict__ c_iso,
                      const float4* __restrict__ c_aniso,
                      const float4* __restrict__ q_iso,
                      const float4* __restrict__ q_aniso,
                      const float*  __restrict__ charge,
                      float4*       __restrict__ out,
                      int B)
{
    const int b    = blockIdx.x;
    const int t    = threadIdx.x;
    const int wid  = t >> 5;
    const int lane = t & 31;
    const size_t row4 = (size_t)b * 1024;   // float4 per 4096-float half-row

    const float4* ci = c_iso   + row4;
    const float4* ca = c_aniso + row4;
    const float4* qi = q_iso   + row4;
    const float4* qa = q_aniso + row4;

    // 8 x float4 loads per thread, front-batched for MLP.
    float4 c0 = ci[t];
    float4 c1 = ci[t + NTHREADS];
    float4 c2 = ca[t];
    float4 c3 = ca[t + NTHREADS];
    float4 q0 = qi[t];
    float4 q1 = qi[t + NTHREADS];
    float4 q2 = qa[t];
    float4 q3 = qa[t + NTHREADS];

    float Qv = (t < NCH) ? charge[(size_t)b * NCH + t] : 0.0f;

    float qc = dot4(q0, c0) + dot4(q1, c1) + dot4(q2, c2) + dot4(q3, c3);
    float qq = dot4(q0, q0) + dot4(q1, q1) + dot4(q2, q2) + dot4(q3, q3);

    // Warp-level butterfly reduction of (qc, qq, Qv).
    #pragma unroll
    for (int m = 16; m; m >>= 1) {
        qc += __shfl_xor_sync(0xffffffffu, qc, m);
        qq += __shfl_xor_sync(0xffffffffu, qq, m);
        Qv += __shfl_xor_sync(0xffffffffu, Qv, m);
    }

    __shared__ float s_p[48];   // [0..16) qc, [16..32) qq, [32..48) Q
    if (lane == 0) { s_p[wid] = qc; s_p[16 + wid] = qq; s_p[32 + wid] = Qv; }
    __syncthreads();            // the ONLY barrier

    // Every warp redundantly reduces the 16 partials — no broadcast,
    // no second barrier.
    float sa = (lane < 16) ? s_p[lane]      : 0.0f;
    float sg = (lane < 16) ? s_p[16 + lane] : 0.0f;
    float sq = (lane < 16) ? s_p[32 + lane] : 0.0f;
    #pragma unroll
    for (int m = 8; m; m >>= 1) {
        sa += __shfl_xor_sync(0xffffffffu, sa, m);
        sg += __shfl_xor_sync(0xffffffffu, sg, m);
        sq += __shfl_xor_sync(0xffffffffu, sq, m);
    }
    const float h = __shfl_sync(0xffffffffu, (sq - sa) / sg, 0);

    float4* oi = out + row4;                      // iso block
    float4* oa = out + (size_t)B * 1024 + row4;   // aniso block

    oi[t]            = axpy4(h, q0, c0);
    oi[t + NTHREADS] = axpy4(h, q1, c1);
    oa[t]            = axpy4(h, q2, c2);
    oa[t + NTHREADS] = axpy4(h, q3, c3);
}

extern "C" void kernel_launch(void* const* d_in, const int* in_sizes, int n_in,
                              void* d_out, int out_size)
{
    const float4* c_iso   = (const float4*)d_in[0];
    const float4* c_aniso = (const float4*)d_in[1];
    const float4* q_iso   = (const float4*)d_in[2];
    const float4* q_aniso = (const float4*)d_in[3];
    const float*  charge  = (const float*) d_in[4];
    float4*       out     = (float4*)d_out;

    const int B = in_sizes[4] / NCH;   // charge is [B, 256]

    qp_charge_norm_kernel<<<B, NTHREADS>>>(c_iso, c_aniso, q_iso, q_aniso,
                                           charge, out, B);
}

// round 12
// speedup vs baseline: 1.5499x; 1.0093x over previous
#include <cuda_runtime.h>

// QPChargeNormalization — best-known architecture (R8: 55.2us kernel, 82.0%
// DRAM) with write-through stores: output (134MB) can't live in L2, so skip
// write-allocate churn and let the read stream keep L2/LTS to itself.
//
// Per row b (B=4096): n=8192, c=[c_iso|c_aniso], q=[int_iso|int_aniso]
//   h = (sum(charge[b]) - q.c) / (q.q),  x = c + h*q
// Output = [sol_iso (B*4096) | sol_aniso (B*4096)]
//
// One CTA per row, 512 threads, 2 CTAs/SM, all data register-resident.
// Single __syncthreads per row; every warp redundantly reduces the 16
// partials so no broadcast / second barrier is needed.

#define NTHREADS 512
#define NCH      256

__device__ __forceinline__ float dot4(float4 a, float4 b) {
    return fmaf(a.x, b.x, fmaf(a.y, b.y, fmaf(a.z, b.z, a.w * b.w)));
}

__device__ __forceinline__ float4 axpy4(float h, float4 q, float4 c) {
    float4 o;
    o.x = fmaf(h, q.x, c.x);
    o.y = fmaf(h, q.y, c.y);
    o.z = fmaf(h, q.z, c.z);
    o.w = fmaf(h, q.w, c.w);
    return o;
}

__device__ __forceinline__ void stwt4(float4* p, float4 v) {
    asm volatile("st.global.wt.v4.f32 [%0], {%1, %2, %3, %4};"
                 :: "l"(p), "f"(v.x), "f"(v.y), "f"(v.z), "f"(v.w) : "memory");
}

__global__ void __launch_bounds__(NTHREADS, 2)
qp_charge_norm_kernel(const float4* __restrict__ c_iso,
                      const float4* __restrict__ c_aniso,
                      const float4* __restrict__ q_iso,
                      const float4* __restrict__ q_aniso,
                      const float*  __restrict__ charge,
                      float4*       __restrict__ out,
                      int B)
{
    const int b    = blockIdx.x;
    const int t    = threadIdx.x;
    const int wid  = t >> 5;
    const int lane = t & 31;
    const size_t row4 = (size_t)b * 1024;   // float4 per 4096-float half-row

    const float4* ci = c_iso   + row4;
    const float4* ca = c_aniso + row4;
    const float4* qi = q_iso   + row4;
    const float4* qa = q_aniso + row4;

    // 8 x float4 loads per thread, front-batched for MLP.
    float4 c0 = ci[t];
    float4 c1 = ci[t + NTHREADS];
    float4 c2 = ca[t];
    float4 c3 = ca[t + NTHREADS];
    float4 q0 = qi[t];
    float4 q1 = qi[t + NTHREADS];
    float4 q2 = qa[t];
    float4 q3 = qa[t + NTHREADS];

    float Qv = (t < NCH) ? charge[(size_t)b * NCH + t] : 0.0f;

    float qc = dot4(q0, c0) + dot4(q1, c1) + dot4(q2, c2) + dot4(q3, c3);
    float qq = dot4(q0, q0) + dot4(q1, q1) + dot4(q2, q2) + dot4(q3, q3);

    // Warp-level butterfly reduction of (qc, qq, Qv).
    #pragma unroll
    for (int m = 16; m; m >>= 1) {
        qc += __shfl_xor_sync(0xffffffffu, qc, m);
        qq += __shfl_xor_sync(0xffffffffu, qq, m);
        Qv += __shfl_xor_sync(0xffffffffu, Qv, m);
    }

    __shared__ float s_p[48];   // [0..16) qc, [16..32) qq, [32..48) Q
    if (lane == 0) { s_p[wid] = qc; s_p[16 + wid] = qq; s_p[32 + wid] = Qv; }
    __syncthreads();            // the ONLY barrier

    // Every warp redundantly reduces the 16 partials — no broadcast,
    // no second barrier.
    float sa = (lane < 16) ? s_p[lane]      : 0.0f;
    float sg = (lane < 16) ? s_p[16 + lane] : 0.0f;
    float sq = (lane < 16) ? s_p[32 + lane] : 0.0f;
    #pragma unroll
    for (int m = 8; m; m >>= 1) {
        sa += __shfl_xor_sync(0xffffffffu, sa, m);
        sg += __shfl_xor_sync(0xffffffffu, sg, m);
        sq += __shfl_xor_sync(0xffffffffu, sq, m);
    }
    const float h = __shfl_sync(0xffffffffu, (sq - sa) / sg, 0);

    float4* oi = out + row4;                      // iso block
    float4* oa = out + (size_t)B * 1024 + row4;   // aniso block

    stwt4(oi + t,            axpy4(h, q0, c0));
    stwt4(oi + t + NTHREADS, axpy4(h, q1, c1));
    stwt4(oa + t,            axpy4(h, q2, c2));
    stwt4(oa + t + NTHREADS, axpy4(h, q3, c3));
}

extern "C" void kernel_launch(void* const* d_in, const int* in_sizes, int n_in,
                              void* d_out, int out_size)
{
    const float4* c_iso   = (const float4*)d_in[0];
    const float4* c_aniso = (const float4*)d_in[1];
    const float4* q_iso   = (const float4*)d_in[2];
    const float4* q_aniso = (const float4*)d_in[3];
    const float*  charge  = (const float*) d_in[4];
    float4*       out     = (float4*)d_out;

    const int B = in_sizes[4] / NCH;   // charge is [B, 256]

    qp_charge_norm_kernel<<<B, NTHREADS>>>(c_iso, c_aniso, q_iso, q_aniso,
                                           charge, out, B);
}